// round 10
// baseline (speedup 1.0000x reference)
#include <cuda_runtime.h>
#include <math.h>

#define NSZ 192
#define NC  16
#define MZ  16     // kz modes
#define MXY 32     // kx / ky modes (16 low + 16 high)
#define NLINE (NC*NSZ)       // 3072
#define NROW  (NC*NSZ*NSZ)   // 589824

// ---------------- scratch (device globals; float4 for 16B alignment) -------
static __device__ float2 Tm[NSZ];                              // (cos, sin) 2*pi*p/192
static __device__ float4 X1q[(size_t)NROW * MZ / 2];           // (c,x,y,kz) cplx
static __device__ float4 X2q[(size_t)NLINE * MXY * MZ / 2];    // (c,x,ky,kz)
static __device__ float4 X3q[(size_t)NC * MXY * MXY * MZ / 2]; // (i,kx,ky,kz)
static __device__ float4 Y3q[(size_t)NC * MXY * MXY * MZ / 2]; // (o,kx,ky,kz)
static __device__ float4 Y2q[(size_t)NLINE * MXY * MZ / 2];    // (c,x,ky,kz)
static __device__ float4 Y1q[(size_t)NROW * MZ / 2];           // (c,x,y,kz)

__device__ __forceinline__ int kmap(int j) { return j < 16 ? j : j + 160; } // 0..15, 176..191

// ---------------- init: master twiddle table --------------------------------
__global__ void k_init() {
  int p = threadIdx.x;
  if (p < NSZ) {
    float s, c;
    sincosf(6.283185307179586f * (float)p / 192.0f, &s, &c);
    Tm[p] = make_float2(c, s);
  }
}

// ---------------- S1: z-DFT, real -> 16 complex modes -----------------------
// rows = (c,x,y) = 589824; out X1[row][kz] = sum_z x[row][z] * e^{-2i pi kz z/192}
// block: 128 thr, 256 rows; thread = (tx: 4 kz-quad, ty: 32) x 8 rows
__global__ void __launch_bounds__(128) k_s1(const float* __restrict__ xg) {
  __shared__ float  xs[32 * 257];      // [z_local][row], pitch 257
  __shared__ float2 tws[32][16];       // [z_local][kz] = (cos, -sin)
  float2* X1 = (float2*)X1q;
  int tid = threadIdx.x;
  int tx = tid & 3, ty = tid >> 2;
  int rowBase = blockIdx.x * 256;

  float2 acc[8][4];
#pragma unroll
  for (int j = 0; j < 8; j++)
#pragma unroll
    for (int q = 0; q < 4; q++) acc[j][q] = make_float2(0.f, 0.f);

  for (int zc = 0; zc < NSZ; zc += 32) {
    __syncthreads();
    for (int i = tid; i < 32 * 16; i += 128) {
      int zl = i >> 4, kz = i & 15;
      int p = (kz * (zc + zl)) % NSZ;
      float2 t = Tm[p];
      tws[zl][kz] = make_float2(t.x, -t.y);
    }
    for (int i = tid; i < 256 * 8; i += 128) {
      int row = i >> 3, u = i & 7;
      float4 v = *(const float4*)(xg + (size_t)(rowBase + row) * NSZ + zc + 4 * u);
      int kb = 4 * u;
      xs[(kb + 0) * 257 + row] = v.x;
      xs[(kb + 1) * 257 + row] = v.y;
      xs[(kb + 2) * 257 + row] = v.z;
      xs[(kb + 3) * 257 + row] = v.w;
    }
    __syncthreads();
#pragma unroll 4
    for (int kk = 0; kk < 32; kk++) {
      float2 t0 = tws[kk][4 * tx + 0];
      float2 t1 = tws[kk][4 * tx + 1];
      float2 t2 = tws[kk][4 * tx + 2];
      float2 t3 = tws[kk][4 * tx + 3];
      const float* xr = &xs[kk * 257 + ty];
#pragma unroll
      for (int j = 0; j < 8; j++) {
        float xv = xr[32 * j];
        acc[j][0].x += xv * t0.x; acc[j][0].y += xv * t0.y;
        acc[j][1].x += xv * t1.x; acc[j][1].y += xv * t1.y;
        acc[j][2].x += xv * t2.x; acc[j][2].y += xv * t2.y;
        acc[j][3].x += xv * t3.x; acc[j][3].y += xv * t3.y;
      }
    }
  }
#pragma unroll
  for (int j = 0; j < 8; j++) {
    int row = rowBase + ty + 32 * j;
#pragma unroll
    for (int q = 0; q < 4; q++)
      X1[(size_t)row * 16 + 4 * tx + q] = acc[j][q];
  }
}

// ---------------- S2: y-DFT, complex, 32 ky modes ----------------------------
// per line (c,x): X2[ky][kz] = sum_y X1[line*192+y][kz] * e^{-2i pi KY(ky) y/192}
// block: 128 thr = 4 lines x 32 threads; thread tile 4 ky x 4 kz
__global__ void __launch_bounds__(128) k_s2() {
  __shared__ float2 x1s[4][48][16];
  __shared__ float2 twy[48][32];       // [y_local][ky] = (cos, -sin)
  float2* X1 = (float2*)X1q;
  float2* X2 = (float2*)X2q;
  int tid = threadIdx.x;
  int l = tid >> 5, lane = tid & 31;
  int kyg = lane >> 2, kzg = lane & 3;
  int lineBase = blockIdx.x * 4;

  float2 acc[4][4];
#pragma unroll
  for (int a = 0; a < 4; a++)
#pragma unroll
    for (int b = 0; b < 4; b++) acc[a][b] = make_float2(0.f, 0.f);

  for (int yc = 0; yc < NSZ; yc += 48) {
    __syncthreads();
    for (int i = tid; i < 48 * 32; i += 128) {
      int yl = i >> 5, ky = i & 31;
      int p = (kmap(ky) * (yc + yl)) % NSZ;
      float2 t = Tm[p];
      twy[yl][ky] = make_float2(t.x, -t.y);
    }
    for (int i = tid; i < 4 * 48 * 8; i += 128) {
      int li = i / 384, rem = i % 384;
      int yl = rem >> 3, u = rem & 7;
      const float4* src = (const float4*)(X1 + ((size_t)(lineBase + li) * NSZ + yc + yl) * 16);
      ((float4*)&x1s[li][yl][0])[u] = src[u];
    }
    __syncthreads();
#pragma unroll 4
    for (int yy = 0; yy < 48; yy++) {
      float2 xv[4], tw[4];
#pragma unroll
      for (int b = 0; b < 4; b++) xv[b] = x1s[l][yy][4 * kzg + b];
#pragma unroll
      for (int a = 0; a < 4; a++) tw[a] = twy[yy][4 * kyg + a];
#pragma unroll
      for (int a = 0; a < 4; a++)
#pragma unroll
        for (int b = 0; b < 4; b++) {
          acc[a][b].x += xv[b].x * tw[a].x - xv[b].y * tw[a].y;
          acc[a][b].y += xv[b].x * tw[a].y + xv[b].y * tw[a].x;
        }
    }
  }
#pragma unroll
  for (int a = 0; a < 4; a++)
#pragma unroll
    for (int b = 0; b < 4; b++)
      X2[((size_t)(lineBase + l) * MXY + 4 * kyg + a) * 16 + 4 * kzg + b] = acc[a][b];
}

// ---------------- S3: x-DFT, complex, 32 kx modes ----------------------------
// block per (c, ky); X3[i,kx,ky,kz] = sum_x X2[c,x,ky,kz] * e^{-2i pi KX(kx) x/192}
__global__ void __launch_bounds__(256) k_s3() {
  __shared__ float2 x2s[192][16];
  __shared__ float2 tml[NSZ];
  float2* X2 = (float2*)X2q;
  float2* X3 = (float2*)X3q;
  int c = blockIdx.x >> 5, ky = blockIdx.x & 31;
  int tid = threadIdx.x;
  int kx = tid & 31, kzp = tid >> 5;   // kz pair {2kzp, 2kzp+1}

  for (int i = tid; i < NSZ; i += 256) tml[i] = Tm[i];
  for (int i = tid; i < 192 * 8; i += 256) {
    int xx = i >> 3, u = i & 7;
    ((float4*)&x2s[xx][0])[u] =
        ((const float4*)(X2 + (((size_t)c * NSZ + xx) * MXY + ky) * 16))[u];
  }
  __syncthreads();

  int kf = kmap(kx);
  float2 acc0 = make_float2(0.f, 0.f), acc1 = make_float2(0.f, 0.f);
  int p = 0;
  for (int xx = 0; xx < NSZ; xx++) {
    float2 t = tml[p];
    float twc = t.x, tws_ = -t.y;
    float2 a = x2s[xx][2 * kzp], b = x2s[xx][2 * kzp + 1];
    acc0.x += a.x * twc - a.y * tws_;
    acc0.y += a.x * tws_ + a.y * twc;
    acc1.x += b.x * twc - b.y * tws_;
    acc1.y += b.x * tws_ + b.y * twc;
    p += kf; if (p >= NSZ) p -= NSZ;
  }
  size_t o = (((size_t)c * MXY + kx) * MXY + ky) * 16 + 2 * kzp;
  X3[o] = acc0;
  X3[o + 1] = acc1;
}

// ---------------- Mix: per-mode 16x16 channel mix with complex weights -------
// block per (kx,ky); thread = (o, kz). Y3[o] = sum_i X3[i] * (wr + i*wi)[q,i,o,mx,my,mz]
__global__ void __launch_bounds__(256) k_mix(const float* __restrict__ wr,
                                             const float* __restrict__ wi) {
  __shared__ float2 xin[16][16];       // [i][kz]
  float2* X3 = (float2*)X3q;
  float2* Y3 = (float2*)Y3q;
  int kx = blockIdx.x >> 5, ky = blockIdx.x & 31;
  int tid = threadIdx.x;
  int kz = tid & 15, o = tid >> 4;
  {
    int i = tid >> 4, z = tid & 15;
    xin[i][z] = X3[(((size_t)i * MXY + kx) * MXY + ky) * 16 + z];
  }
  __syncthreads();
  int q = (kx >= 16 ? 1 : 0) + (ky >= 16 ? 2 : 0);
  int mx = kx & 15, my = ky & 15;
  int moff = mx * 256 + my * 16 + kz;
  float2 acc = make_float2(0.f, 0.f);
#pragma unroll
  for (int i = 0; i < 16; i++) {
    int widx = ((q * 16 + i) * 16 + o) * 4096 + moff;
    float wrv = wr[widx], wiv = wi[widx];
    float2 xv = xin[i][kz];
    acc.x += xv.x * wrv - xv.y * wiv;
    acc.y += xv.x * wiv + xv.y * wrv;
  }
  Y3[(((size_t)o * MXY + kx) * MXY + ky) * 16 + kz] = acc;
}

// ---------------- I1: inverse x (32 modes -> 192 x) --------------------------
// block per (c, ky, half of x); thread = (xg 16 x 6 x-vals, kz 16)
__global__ void __launch_bounds__(256) k_i1() {
  __shared__ float2 y3s[32][16];
  __shared__ float2 twx[32][96];       // (cos, +sin)
  float2* Y3 = (float2*)Y3q;
  float2* Y2 = (float2*)Y2q;
  int bb = blockIdx.x;
  int half = bb & 1, ky = (bb >> 1) & 31, c = bb >> 6;
  int x0 = half * 96;
  int tid = threadIdx.x;
  int kz = tid & 15, xg = tid >> 4;

  for (int i = tid; i < 32 * 16; i += 256) {
    int kx = i >> 4, z = i & 15;
    y3s[kx][z] = Y3[(((size_t)c * MXY + kx) * MXY + ky) * 16 + z];
  }
  for (int i = tid; i < 32 * 96; i += 256) {
    int kx = i / 96, xl = i % 96;
    int p = (kmap(kx) * (x0 + xl)) % NSZ;
    twx[kx][xl] = Tm[p];
  }
  __syncthreads();

  float2 acc[6];
#pragma unroll
  for (int m = 0; m < 6; m++) acc[m] = make_float2(0.f, 0.f);
#pragma unroll 4
  for (int kx = 0; kx < 32; kx++) {
    float2 yv = y3s[kx][kz];
#pragma unroll
    for (int m = 0; m < 6; m++) {
      float2 t = twx[kx][xg * 6 + m];
      acc[m].x += yv.x * t.x - yv.y * t.y;
      acc[m].y += yv.x * t.y + yv.y * t.x;
    }
  }
#pragma unroll
  for (int m = 0; m < 6; m++)
    Y2[(((size_t)c * NSZ + x0 + xg * 6 + m) * MXY + ky) * 16 + kz] = acc[m];
}

// ---------------- I2: inverse y (32 modes -> 192 y) --------------------------
// block per (line = c*192+x, half of y)
__global__ void __launch_bounds__(256) k_i2() {
  __shared__ float2 y2s[32][16];
  __shared__ float2 twy[32][96];       // (cos, +sin)
  float2* Y2 = (float2*)Y2q;
  float2* Y1 = (float2*)Y1q;
  int bb = blockIdx.x;
  int half = bb & 1;
  size_t line = (size_t)(bb >> 1);
  int y0 = half * 96;
  int tid = threadIdx.x;
  int kz = tid & 15, yg = tid >> 4;

  for (int i = tid; i < 32 * 16; i += 256) {
    int ky = i >> 4, z = i & 15;
    y2s[ky][z] = Y2[(line * MXY + ky) * 16 + z];
  }
  for (int i = tid; i < 32 * 96; i += 256) {
    int ky = i / 96, yl = i % 96;
    int p = (kmap(ky) * (y0 + yl)) % NSZ;
    twy[ky][yl] = Tm[p];
  }
  __syncthreads();

  float2 acc[6];
#pragma unroll
  for (int m = 0; m < 6; m++) acc[m] = make_float2(0.f, 0.f);
#pragma unroll 4
  for (int ky = 0; ky < 32; ky++) {
    float2 yv = y2s[ky][kz];
#pragma unroll
    for (int m = 0; m < 6; m++) {
      float2 t = twy[ky][yg * 6 + m];
      acc[m].x += yv.x * t.x - yv.y * t.y;
      acc[m].y += yv.x * t.y + yv.y * t.x;
    }
  }
#pragma unroll
  for (int m = 0; m < 6; m++)
    Y1[(line * NSZ + y0 + yg * 6 + m) * 16 + kz] = acc[m];
}

// ---------------- I3: inverse z C2R (16 modes -> 192 real), includes 1/N^3 ---
// out[row][z] = sum_k alpha_k*(Re*cos - Im*sin), alpha_0=inv, alpha_k=2inv
// block: 256 thr, 64 rows x 192 z; thread = (tx: 32 z-lanes, ty: 8) x 8 rows x 6 z
__global__ void __launch_bounds__(256) k_i3(float* __restrict__ out) {
  __shared__ float2 ys[64][16];        // 8 KB
  __shared__ float2 twz[16][192];      // 24 KB, (a*cos, -a*sin)
  float2* Y1 = (float2*)Y1q;
  size_t rowBase = (size_t)blockIdx.x * 64;
  int tid = threadIdx.x;
  int tx = tid & 31, ty = tid >> 5;

  for (int i = tid; i < 512; i += 256)
    ((float4*)ys)[i] = ((const float4*)(Y1 + rowBase * 16))[i];

  const float inv = 1.0f / (192.0f * 192.0f * 192.0f);
  for (int i = tid; i < 16 * 192; i += 256) {
    int k = i / 192, z = i % 192;
    int p = (k * z) % NSZ;
    float2 t = Tm[p];
    float a = (k == 0) ? inv : 2.0f * inv;
    twz[k][z] = make_float2(a * t.x, -a * t.y);
  }
  __syncthreads();

  float acc[8][6];
#pragma unroll
  for (int j = 0; j < 8; j++)
#pragma unroll
    for (int m = 0; m < 6; m++) acc[j][m] = 0.f;

#pragma unroll 2
  for (int k = 0; k < 16; k++) {
    float2 tw[6];
#pragma unroll
    for (int m = 0; m < 6; m++) tw[m] = twz[k][tx + 32 * m];
#pragma unroll
    for (int j = 0; j < 8; j++) {
      float2 yv = ys[ty * 8 + j][k];
#pragma unroll
      for (int m = 0; m < 6; m++)
        acc[j][m] += yv.x * tw[m].x + yv.y * tw[m].y;
    }
  }
#pragma unroll
  for (int j = 0; j < 8; j++) {
    size_t ob = (rowBase + ty * 8 + j) * NSZ + tx;
#pragma unroll
    for (int m = 0; m < 6; m++)
      out[ob + 32 * m] = acc[j][m];
  }
}

// ---------------- launch ------------------------------------------------------
extern "C" void kernel_launch(void* const* d_in, const int* in_sizes, int n_in,
                              void* d_out, int out_size) {
  (void)in_sizes; (void)n_in; (void)out_size;
  const float* x  = (const float*)d_in[0];
  const float* wr = (const float*)d_in[1];
  const float* wi = (const float*)d_in[2];

  k_init<<<1, 192>>>();
  k_s1 <<<NROW / 256, 128>>>(x);          // 2304 blocks
  k_s2 <<<NLINE / 4, 128>>>();            // 768 blocks
  k_s3 <<<NC * MXY, 256>>>();             // 512 blocks
  k_mix<<<MXY * MXY, 256>>>(wr, wi);      // 1024 blocks
  k_i1 <<<NC * MXY * 2, 256>>>();         // 1024 blocks
  k_i2 <<<NLINE * 2, 256>>>();            // 6144 blocks
  k_i3 <<<NROW / 64, 256>>>((float*)d_out); // 9216 blocks
}

// round 11
// speedup vs baseline: 1.0020x; 1.0020x over previous
#include <cuda_runtime.h>
#include <math.h>

#define NSZ 192
#define NC  16
#define MZ  16     // kz modes
#define MXY 32     // kx / ky modes (16 low + 16 high)
#define NLINE (NC*NSZ)       // 3072
#define NROW  (NC*NSZ*NSZ)   // 589824

// ---------------- scratch (device globals; float4 for 16B alignment) -------
static __device__ float2 Tm[NSZ];                              // (cos, sin) 2*pi*p/192
static __device__ float4 X1q[(size_t)NROW * MZ / 2];           // (c,x,y,kz) cplx
static __device__ float4 X2q[(size_t)NLINE * MXY * MZ / 2];    // (c,x,ky,kz)
static __device__ float4 X3q[(size_t)NC * MXY * MXY * MZ / 2]; // (i,kx,ky,kz)
static __device__ float4 Y3q[(size_t)NC * MXY * MXY * MZ / 2]; // (o,kx,ky,kz)
static __device__ float4 Y2q[(size_t)NLINE * MXY * MZ / 2];    // (c,x,ky,kz)
static __device__ float4 Y1q[(size_t)NROW * MZ / 2];           // (c,x,y,kz)

__device__ __forceinline__ int kmap(int j) { return j < 16 ? j : j + 160; } // 0..15, 176..191

// ---------------- init: master twiddle table --------------------------------
__global__ void k_init() {
  int p = threadIdx.x;
  if (p < NSZ) {
    float s, c;
    sincosf(6.283185307179586f * (float)p / 192.0f, &s, &c);
    Tm[p] = make_float2(c, s);
  }
}

// ---------------- S1: z-DFT, real -> 16 complex modes -----------------------
// rows = (c,x,y) = 589824; out X1[row][kz] = sum_z x[row][z] * e^{-2i pi kz z/192}
// block: 128 thr, 256 rows; thread = (tx: 4 kz-quad, ty: 32) x 8 rows
__global__ void __launch_bounds__(128) k_s1(const float* __restrict__ xg) {
  __shared__ float  xs[32 * 257];      // [z_local][row], pitch 257
  __shared__ float2 tws[32][16];       // [z_local][kz] = (cos, -sin)
  float2* X1 = (float2*)X1q;
  int tid = threadIdx.x;
  int tx = tid & 3, ty = tid >> 2;
  int rowBase = blockIdx.x * 256;

  float2 acc[8][4];
#pragma unroll
  for (int j = 0; j < 8; j++)
#pragma unroll
    for (int q = 0; q < 4; q++) acc[j][q] = make_float2(0.f, 0.f);

  for (int zc = 0; zc < NSZ; zc += 32) {
    __syncthreads();
    for (int i = tid; i < 32 * 16; i += 128) {
      int zl = i >> 4, kz = i & 15;
      int p = (kz * (zc + zl)) % NSZ;
      float2 t = Tm[p];
      tws[zl][kz] = make_float2(t.x, -t.y);
    }
    for (int i = tid; i < 256 * 8; i += 128) {
      int row = i >> 3, u = i & 7;
      float4 v = *(const float4*)(xg + (size_t)(rowBase + row) * NSZ + zc + 4 * u);
      int kb = 4 * u;
      xs[(kb + 0) * 257 + row] = v.x;
      xs[(kb + 1) * 257 + row] = v.y;
      xs[(kb + 2) * 257 + row] = v.z;
      xs[(kb + 3) * 257 + row] = v.w;
    }
    __syncthreads();
#pragma unroll 4
    for (int kk = 0; kk < 32; kk++) {
      float2 t0 = tws[kk][4 * tx + 0];
      float2 t1 = tws[kk][4 * tx + 1];
      float2 t2 = tws[kk][4 * tx + 2];
      float2 t3 = tws[kk][4 * tx + 3];
      const float* xr = &xs[kk * 257 + ty];
#pragma unroll
      for (int j = 0; j < 8; j++) {
        float xv = xr[32 * j];
        acc[j][0].x += xv * t0.x; acc[j][0].y += xv * t0.y;
        acc[j][1].x += xv * t1.x; acc[j][1].y += xv * t1.y;
        acc[j][2].x += xv * t2.x; acc[j][2].y += xv * t2.y;
        acc[j][3].x += xv * t3.x; acc[j][3].y += xv * t3.y;
      }
    }
  }
#pragma unroll
  for (int j = 0; j < 8; j++) {
    int row = rowBase + ty + 32 * j;
#pragma unroll
    for (int q = 0; q < 4; q++)
      X1[(size_t)row * 16 + 4 * tx + q] = acc[j][q];
  }
}

// ---------------- S2: y-DFT, complex, 32 ky modes ----------------------------
// per line (c,x): X2[ky][kz] = sum_y X1[line*192+y][kz] * e^{-2i pi KY(ky) y/192}
// block: 128 thr = 4 lines x 32 threads; thread tile 4 ky x 4 kz
__global__ void __launch_bounds__(128) k_s2() {
  __shared__ float2 x1s[4][48][16];
  __shared__ float2 twy[48][32];       // [y_local][ky] = (cos, -sin)
  float2* X1 = (float2*)X1q;
  float2* X2 = (float2*)X2q;
  int tid = threadIdx.x;
  int l = tid >> 5, lane = tid & 31;
  int kyg = lane >> 2, kzg = lane & 3;
  int lineBase = blockIdx.x * 4;

  float2 acc[4][4];
#pragma unroll
  for (int a = 0; a < 4; a++)
#pragma unroll
    for (int b = 0; b < 4; b++) acc[a][b] = make_float2(0.f, 0.f);

  for (int yc = 0; yc < NSZ; yc += 48) {
    __syncthreads();
    for (int i = tid; i < 48 * 32; i += 128) {
      int yl = i >> 5, ky = i & 31;
      int p = (kmap(ky) * (yc + yl)) % NSZ;
      float2 t = Tm[p];
      twy[yl][ky] = make_float2(t.x, -t.y);
    }
    for (int i = tid; i < 4 * 48 * 8; i += 128) {
      int li = i / 384, rem = i % 384;
      int yl = rem >> 3, u = rem & 7;
      const float4* src = (const float4*)(X1 + ((size_t)(lineBase + li) * NSZ + yc + yl) * 16);
      ((float4*)&x1s[li][yl][0])[u] = src[u];
    }
    __syncthreads();
#pragma unroll 4
    for (int yy = 0; yy < 48; yy++) {
      float2 xv[4], tw[4];
#pragma unroll
      for (int b = 0; b < 4; b++) xv[b] = x1s[l][yy][4 * kzg + b];
#pragma unroll
      for (int a = 0; a < 4; a++) tw[a] = twy[yy][4 * kyg + a];
#pragma unroll
      for (int a = 0; a < 4; a++)
#pragma unroll
        for (int b = 0; b < 4; b++) {
          acc[a][b].x += xv[b].x * tw[a].x - xv[b].y * tw[a].y;
          acc[a][b].y += xv[b].x * tw[a].y + xv[b].y * tw[a].x;
        }
    }
  }
#pragma unroll
  for (int a = 0; a < 4; a++)
#pragma unroll
    for (int b = 0; b < 4; b++)
      X2[((size_t)(lineBase + l) * MXY + 4 * kyg + a) * 16 + 4 * kzg + b] = acc[a][b];
}

// ---------------- S3: x-DFT, complex, 32 kx modes ----------------------------
// block per (c, ky); X3[i,kx,ky,kz] = sum_x X2[c,x,ky,kz] * e^{-2i pi KX(kx) x/192}
__global__ void __launch_bounds__(256) k_s3() {
  __shared__ float2 x2s[192][16];
  __shared__ float2 tml[NSZ];
  float2* X2 = (float2*)X2q;
  float2* X3 = (float2*)X3q;
  int c = blockIdx.x >> 5, ky = blockIdx.x & 31;
  int tid = threadIdx.x;
  int kx = tid & 31, kzp = tid >> 5;   // kz pair {2kzp, 2kzp+1}

  for (int i = tid; i < NSZ; i += 256) tml[i] = Tm[i];
  for (int i = tid; i < 192 * 8; i += 256) {
    int xx = i >> 3, u = i & 7;
    ((float4*)&x2s[xx][0])[u] =
        ((const float4*)(X2 + (((size_t)c * NSZ + xx) * MXY + ky) * 16))[u];
  }
  __syncthreads();

  int kf = kmap(kx);
  float2 acc0 = make_float2(0.f, 0.f), acc1 = make_float2(0.f, 0.f);
  int p = 0;
  for (int xx = 0; xx < NSZ; xx++) {
    float2 t = tml[p];
    float twc = t.x, tws_ = -t.y;
    float2 a = x2s[xx][2 * kzp], b = x2s[xx][2 * kzp + 1];
    acc0.x += a.x * twc - a.y * tws_;
    acc0.y += a.x * tws_ + a.y * twc;
    acc1.x += b.x * twc - b.y * tws_;
    acc1.y += b.x * tws_ + b.y * twc;
    p += kf; if (p >= NSZ) p -= NSZ;
  }
  size_t o = (((size_t)c * MXY + kx) * MXY + ky) * 16 + 2 * kzp;
  X3[o] = acc0;
  X3[o + 1] = acc1;
}

// ---------------- Mix: per-mode 16x16 channel mix with complex weights -------
// block per (kx,ky); thread = (o, kz). Y3[o] = sum_i X3[i] * (wr + i*wi)[q,i,o,mx,my,mz]
__global__ void __launch_bounds__(256) k_mix(const float* __restrict__ wr,
                                             const float* __restrict__ wi) {
  __shared__ float2 xin[16][16];       // [i][kz]
  float2* X3 = (float2*)X3q;
  float2* Y3 = (float2*)Y3q;
  int kx = blockIdx.x >> 5, ky = blockIdx.x & 31;
  int tid = threadIdx.x;
  int kz = tid & 15, o = tid >> 4;
  {
    int i = tid >> 4, z = tid & 15;
    xin[i][z] = X3[(((size_t)i * MXY + kx) * MXY + ky) * 16 + z];
  }
  __syncthreads();
  int q = (kx >= 16 ? 1 : 0) + (ky >= 16 ? 2 : 0);
  int mx = kx & 15, my = ky & 15;
  int moff = mx * 256 + my * 16 + kz;
  float2 acc = make_float2(0.f, 0.f);
#pragma unroll
  for (int i = 0; i < 16; i++) {
    int widx = ((q * 16 + i) * 16 + o) * 4096 + moff;
    float wrv = wr[widx], wiv = wi[widx];
    float2 xv = xin[i][kz];
    acc.x += xv.x * wrv - xv.y * wiv;
    acc.y += xv.x * wiv + xv.y * wrv;
  }
  Y3[(((size_t)o * MXY + kx) * MXY + ky) * 16 + kz] = acc;
}

// ---------------- I1: inverse x (32 modes -> 192 x) --------------------------
// block per (c, ky, half of x); thread = (xg 16 x 6 x-vals, kz 16)
__global__ void __launch_bounds__(256) k_i1() {
  __shared__ float2 y3s[32][16];
  __shared__ float2 twx[32][96];       // (cos, +sin)
  float2* Y3 = (float2*)Y3q;
  float2* Y2 = (float2*)Y2q;
  int bb = blockIdx.x;
  int half = bb & 1, ky = (bb >> 1) & 31, c = bb >> 6;
  int x0 = half * 96;
  int tid = threadIdx.x;
  int kz = tid & 15, xg = tid >> 4;

  for (int i = tid; i < 32 * 16; i += 256) {
    int kx = i >> 4, z = i & 15;
    y3s[kx][z] = Y3[(((size_t)c * MXY + kx) * MXY + ky) * 16 + z];
  }
  for (int i = tid; i < 32 * 96; i += 256) {
    int kx = i / 96, xl = i % 96;
    int p = (kmap(kx) * (x0 + xl)) % NSZ;
    twx[kx][xl] = Tm[p];
  }
  __syncthreads();

  float2 acc[6];
#pragma unroll
  for (int m = 0; m < 6; m++) acc[m] = make_float2(0.f, 0.f);
#pragma unroll 4
  for (int kx = 0; kx < 32; kx++) {
    float2 yv = y3s[kx][kz];
#pragma unroll
    for (int m = 0; m < 6; m++) {
      float2 t = twx[kx][xg * 6 + m];
      acc[m].x += yv.x * t.x - yv.y * t.y;
      acc[m].y += yv.x * t.y + yv.y * t.x;
    }
  }
#pragma unroll
  for (int m = 0; m < 6; m++)
    Y2[(((size_t)c * NSZ + x0 + xg * 6 + m) * MXY + ky) * 16 + kz] = acc[m];
}

// ---------------- I2: inverse y (32 modes -> 192 y) --------------------------
// block per (line = c*192+x, half of y)
__global__ void __launch_bounds__(256) k_i2() {
  __shared__ float2 y2s[32][16];
  __shared__ float2 twy[32][96];       // (cos, +sin)
  float2* Y2 = (float2*)Y2q;
  float2* Y1 = (float2*)Y1q;
  int bb = blockIdx.x;
  int half = bb & 1;
  size_t line = (size_t)(bb >> 1);
  int y0 = half * 96;
  int tid = threadIdx.x;
  int kz = tid & 15, yg = tid >> 4;

  for (int i = tid; i < 32 * 16; i += 256) {
    int ky = i >> 4, z = i & 15;
    y2s[ky][z] = Y2[(line * MXY + ky) * 16 + z];
  }
  for (int i = tid; i < 32 * 96; i += 256) {
    int ky = i / 96, yl = i % 96;
    int p = (kmap(ky) * (y0 + yl)) % NSZ;
    twy[ky][yl] = Tm[p];
  }
  __syncthreads();

  float2 acc[6];
#pragma unroll
  for (int m = 0; m < 6; m++) acc[m] = make_float2(0.f, 0.f);
#pragma unroll 4
  for (int ky = 0; ky < 32; ky++) {
    float2 yv = y2s[ky][kz];
#pragma unroll
    for (int m = 0; m < 6; m++) {
      float2 t = twy[ky][yg * 6 + m];
      acc[m].x += yv.x * t.x - yv.y * t.y;
      acc[m].y += yv.x * t.y + yv.y * t.x;
    }
  }
#pragma unroll
  for (int m = 0; m < 6; m++)
    Y1[(line * NSZ + y0 + yg * 6 + m) * 16 + kz] = acc[m];
}

// ---------------- I3: inverse z C2R (16 modes -> 192 real), includes 1/N^3 ---
// out[row][z] = sum_k alpha_k*(Re*cos - Im*sin), alpha_0=inv, alpha_k=2inv
// block: 256 thr, 64 rows x 192 z; thread = (tx: 32 z-lanes, ty: 8) x 8 rows x 6 z
__global__ void __launch_bounds__(256) k_i3(float* __restrict__ out) {
  __shared__ float2 ys[64][16];        // 8 KB
  __shared__ float2 twz[16][192];      // 24 KB, (a*cos, -a*sin)
  float2* Y1 = (float2*)Y1q;
  size_t rowBase = (size_t)blockIdx.x * 64;
  int tid = threadIdx.x;
  int tx = tid & 31, ty = tid >> 5;

  for (int i = tid; i < 512; i += 256)
    ((float4*)ys)[i] = ((const float4*)(Y1 + rowBase * 16))[i];

  const float inv = 1.0f / (192.0f * 192.0f * 192.0f);
  for (int i = tid; i < 16 * 192; i += 256) {
    int k = i / 192, z = i % 192;
    int p = (k * z) % NSZ;
    float2 t = Tm[p];
    float a = (k == 0) ? inv : 2.0f * inv;
    twz[k][z] = make_float2(a * t.x, -a * t.y);
  }
  __syncthreads();

  float acc[8][6];
#pragma unroll
  for (int j = 0; j < 8; j++)
#pragma unroll
    for (int m = 0; m < 6; m++) acc[j][m] = 0.f;

#pragma unroll 2
  for (int k = 0; k < 16; k++) {
    float2 tw[6];
#pragma unroll
    for (int m = 0; m < 6; m++) tw[m] = twz[k][tx + 32 * m];
#pragma unroll
    for (int j = 0; j < 8; j++) {
      float2 yv = ys[ty * 8 + j][k];
#pragma unroll
      for (int m = 0; m < 6; m++)
        acc[j][m] += yv.x * tw[m].x + yv.y * tw[m].y;
    }
  }
#pragma unroll
  for (int j = 0; j < 8; j++) {
    size_t ob = (rowBase + ty * 8 + j) * NSZ + tx;
#pragma unroll
    for (int m = 0; m < 6; m++)
      out[ob + 32 * m] = acc[j][m];
  }
}

// ---------------- launch ------------------------------------------------------
extern "C" void kernel_launch(void* const* d_in, const int* in_sizes, int n_in,
                              void* d_out, int out_size) {
  (void)in_sizes; (void)n_in; (void)out_size;
  const float* x  = (const float*)d_in[0];
  const float* wr = (const float*)d_in[1];
  const float* wi = (const float*)d_in[2];

  k_init<<<1, 192>>>();
  k_s1 <<<NROW / 256, 128>>>(x);          // 2304 blocks
  k_s2 <<<NLINE / 4, 128>>>();            // 768 blocks
  k_s3 <<<NC * MXY, 256>>>();             // 512 blocks
  k_mix<<<MXY * MXY, 256>>>(wr, wi);      // 1024 blocks
  k_i1 <<<NC * MXY * 2, 256>>>();         // 1024 blocks
  k_i2 <<<NLINE * 2, 256>>>();            // 6144 blocks
  k_i3 <<<NROW / 64, 256>>>((float*)d_out); // 9216 blocks
}